// round 13
// baseline (speedup 1.0000x reference)
#include <cuda_runtime.h>
#include <math.h>

#define B    16
#define T    12
#define NN   8600
#define H    64
#define E2   128
#define KK   66
#define RPASS 128                                 // rows (nodes) per CTA
#define CHUNKS ((NN + RPASS - 1) / RPASS)         // 68
#define SROW 67                                   // padded row stride (bank-safe)
#define NT   512                                  // threads per CTA (16 warps)
#define OUT_LAST_OFF ((size_t)B * T * NN * H)

typedef unsigned long long ull;

// ---------------- scratch (device globals; no allocation allowed) --------------
__device__ __align__(16) float g_agg_gate[2][B * E2];
__device__ __align__(16) float g_agg_upd[2][B * H];
__device__ __align__(128) float g_r[(size_t)B * NN * H];     // gate r    (35.2 MB)
__device__ __align__(128) float g_resu[(size_t)B * NN * H];  // res_upd   (35.2 MB)

// ---------------- f32x2 helpers ------------------------------------------------
__device__ __forceinline__ ull pack2(float a) {
    ull r; unsigned int u = __float_as_uint(a);
    asm("mov.b64 %0, {%1, %1};" : "=l"(r) : "r"(u));
    return r;
}
__device__ __forceinline__ void fma2(ull& d, ull a, ull b) {
    asm("fma.rn.f32x2 %0, %1, %2, %3;" : "=l"(d) : "l"(a), "l"(b), "l"(d));
}
__device__ __forceinline__ void unpack2(ull v, float& x, float& y) {
    asm("mov.b64 {%0, %1}, %2;" : "=f"(x), "=f"(y) : "l"(v));
}
__device__ __forceinline__ float sigmoidf_(float x) {
    return 1.0f / (1.0f + __expf(-x));
}

// dot: warp covers 64 rows x 16 cols. lane l -> rows rbase+l, rbase+l+32.
// acc[m][j] accumulates (col e0+2j, e0+2j+1) for row-group m.
__device__ __forceinline__ void dot64(const float* __restrict__ sin_,
                                      const float* __restrict__ sW,
                                      int rbase, int lane, int e0, ull acc[2][8]) {
    const float* r0 = sin_ + (rbase + lane) * SROW;
    const float* r1 = r0 + 32 * SROW;
    const float* wp = sW + e0;
#pragma unroll 2
    for (int k = 0; k < KK; k++) {
        ull a0 = pack2(r0[k]);
        ull a1 = pack2(r1[k]);
        const ulonglong2* w2 = (const ulonglong2*)(wp + (size_t)k * E2);
        ulonglong2 p0 = w2[0], p1 = w2[1];
        fma2(acc[0][0], a0, p0.x); fma2(acc[0][1], a0, p0.y);
        fma2(acc[1][0], a1, p0.x); fma2(acc[1][1], a1, p0.y);
        fma2(acc[0][2], a0, p1.x); fma2(acc[0][3], a0, p1.y);
        fma2(acc[1][2], a1, p1.x); fma2(acc[1][3], a1, p1.y);
        ulonglong2 p2 = w2[2], p3 = w2[3];
        fma2(acc[0][4], a0, p2.x); fma2(acc[0][5], a0, p2.y);
        fma2(acc[1][4], a1, p2.x); fma2(acc[1][5], a1, p2.y);
        fma2(acc[0][6], a0, p3.x); fma2(acc[0][7], a0, p3.y);
        fma2(acc[1][6], a1, p3.x); fma2(acc[1][7], a1, p3.y);
    }
}

// per-warp column reduction + atomic (colsum[16], each lane holds partial)
__device__ __forceinline__ void colreduce_atomic(float colsum[16], int lane,
                                                 float* dst) {
#pragma unroll
    for (int j = 0; j < 16; j++) {
        float v = colsum[j];
#pragma unroll
        for (int o = 16; o > 0; o >>= 1) v += __shfl_xor_sync(0xffffffffu, v, o);
        colsum[j] = v;
    }
    if (lane == 0) {
#pragma unroll
        for (int j = 0; j < 16; j++) atomicAdd(dst + j, colsum[j]);
    }
}

extern __shared__ float sdyn[];

// =========================== prologue zero =====================================
__global__ void k_zero0() {
    int i = blockIdx.x * blockDim.x + threadIdx.x;
    if (i < B * E2) g_agg_gate[0][i] = 0.0f;
    if (i < B * H)  g_agg_upd[0][i] = 0.0f;
}

// stage [x(2) | state(64)] rows into sin_ (128 rows x SROW), NT=512 threads
__device__ __forceinline__ void stage_input(float* sin_, const float* xb,
                                            const float* stb, int base, int tid) {
#pragma unroll
    for (int p = 0; p < 4; p++) {
        int slot = p * NT + tid;           // 2048 slots = 128 rows x 16 float4
        int row = slot >> 4, q = (slot & 15) * 4;
        int n = base + row;
        float4 v = make_float4(0.f, 0.f, 0.f, 0.f);
        if (n < NN) v = *(const float4*)(stb + (size_t)n * H + q);
        float* d = sin_ + row * SROW + 2 + q;
        d[0] = v.x; d[1] = v.y; d[2] = v.z; d[3] = v.w;
    }
    if (tid < 256) {
        int row = tid >> 1, kx = tid & 1;
        int n = base + row;
        sin_[row * SROW + kx] = (n < NN) ? xb[(size_t)n * 2 + kx] : 0.0f;
    }
}

// ========== K1 (t=0 only): relu([x,state] @ gate_w + b), agg over nodes ========
__global__ void __launch_bounds__(NT, 2) k_gate_agg(
    const float* __restrict__ x, const float* __restrict__ state, int sstr,
    const float* __restrict__ Wg, const float* __restrict__ bg, int t, int pg)
{
    float* sW   = sdyn;              // 66*128
    float* sb   = sW + KK * E2;      // 128
    float* sin_ = sb + E2;           // 128*67

    int tid = threadIdx.x;
    int b = blockIdx.y;
    int base = blockIdx.x * RPASS;

    for (int i = tid; i < KK * E2 / 4; i += NT)
        ((float4*)sW)[i] = ((const float4*)Wg)[i];
    if (tid < E2) sb[tid] = bg[tid];

    const float* xb  = x + (size_t)(b * T + t) * NN * 2;
    const float* stb = state + (size_t)b * sstr;
    stage_input(sin_, xb, stb, base, tid);
    __syncthreads();

    int w = tid >> 5, lane = tid & 31;
    int rbase = (w >> 3) * 64, e0 = (w & 7) * 16;

    ull acc[2][8];
#pragma unroll
    for (int m = 0; m < 2; m++)
#pragma unroll
        for (int j = 0; j < 8; j++) acc[m][j] = 0ULL;
    dot64(sin_, sW, rbase, lane, e0, acc);

    float colsum[16];
#pragma unroll
    for (int j = 0; j < 16; j++) colsum[j] = 0.0f;
#pragma unroll
    for (int m = 0; m < 2; m++) {
        int n = base + rbase + lane + 32 * m;
        if (n < NN) {
#pragma unroll
            for (int j = 0; j < 8; j++) {
                float v0, v1; unpack2(acc[m][j], v0, v1);
                colsum[2*j]   += fmaxf(v0 + sb[e0 + 2*j],     0.0f);
                colsum[2*j+1] += fmaxf(v1 + sb[e0 + 2*j + 1], 0.0f);
            }
        }
    }
    colreduce_atomic(colsum, lane, &g_agg_gate[pg][b * E2 + e0]);
}

// ===== K2: sigmoid(zr) via agg_gate; in-place z*state; upd dot; r/resu/agg =====
__global__ void __launch_bounds__(NT, 2) k_mid(
    const float* __restrict__ x, const float* __restrict__ state, int sstr,
    const float* __restrict__ Wga, const float* __restrict__ bga,
    const float* __restrict__ Wuw, const float* __restrict__ buw,
    const float* __restrict__ Wua, const float* __restrict__ bua,
    const float* __restrict__ affw, const float* __restrict__ affb,
    const float* __restrict__ nodew, const float* __restrict__ addw,
    int t, int pg, int pn)
{
    float* sWa  = sdyn;               // 66*128 gate_align_w
    float* sWu  = sWa + KK * E2;      // 66*128 [upd_w | upd_align_w]
    float* sba  = sWu + KK * E2;      // 128
    float* sbu  = sba + E2;           // 128
    float* sagg = sbu + E2;           // 128
    float* sin_ = sagg + E2;          // 128*67

    int tid = threadIdx.x;
    int b = blockIdx.y;
    int base = blockIdx.x * RPASS;

    if (blockIdx.x == 0 && blockIdx.y == 0) {     // zero next-parity agg buffers
        for (int i = tid; i < B * E2; i += NT) g_agg_gate[pn][i] = 0.0f;
        for (int i = tid; i < B * H;  i += NT) g_agg_upd[pn][i] = 0.0f;
    }

    for (int i = tid; i < KK * E2 / 4; i += NT)
        ((float4*)sWa)[i] = ((const float4*)Wga)[i];
    for (int i = tid; i < KK * H / 4; i += NT) {
        int k = i / (H / 4), g = i % (H / 4);
        ((float4*)sWu)[k * 32 + g]      = ((const float4*)Wuw)[i];
        ((float4*)sWu)[k * 32 + 16 + g] = ((const float4*)Wua)[i];
    }
    if (tid < E2) {
        sba[tid]  = bga[tid];
        sbu[tid]  = (tid < H) ? buw[tid] : bua[tid - H];
        sagg[tid] = g_agg_gate[pg][b * E2 + tid];
    }

    const float* xb  = x + (size_t)(b * T + t) * NN * 2;
    const float* stb = state + (size_t)b * sstr;
    stage_input(sin_, xb, stb, base, tid);
    __syncthreads();

    int w = tid >> 5, lane = tid & 31;
    int rbase = (w >> 3) * 64, e0 = (w & 7) * 16;
    bool is_z = ((w & 7) < 4);                    // cols 0..63 vs 64..127

    // ---- gate-align dot ----
    ull acc[2][8];
#pragma unroll
    for (int m = 0; m < 2; m++)
#pragma unroll
        for (int j = 0; j < 8; j++) acc[m][j] = 0ULL;
    dot64(sin_, sWa, rbase, lane, e0, acc);

    // ---- zr epilogue (per lane: 2 rows x 16 cols) ----
    float zr[2][16];
#pragma unroll
    for (int m = 0; m < 2; m++) {
        int n = base + rbase + lane + 32 * m;
        if (n < NN) {
            float sgn = addw[n] * nodew[n];
            float aw[16], ab[16];
            const float4* awp = (const float4*)&affw[(size_t)n * E2 + e0];
            const float4* abp = (const float4*)&affb[(size_t)n * E2 + e0];
#pragma unroll
            for (int q = 0; q < 4; q++) {
                ((float4*)aw)[q] = awp[q];
                ((float4*)ab)[q] = abp[q];
            }
#pragma unroll
            for (int j = 0; j < 8; j++) {
                float v0, v1; unpack2(acc[m][j], v0, v1);
                float p0 = v0 + sba[e0 + 2*j]
                         + aw[2*j]   * sgn * sagg[e0 + 2*j]     + ab[2*j];
                float p1 = v1 + sba[e0 + 2*j + 1]
                         + aw[2*j+1] * sgn * sagg[e0 + 2*j + 1] + ab[2*j+1];
                zr[m][2*j]   = sigmoidf_(p0);
                zr[m][2*j+1] = sigmoidf_(p1);
            }
        } else {
#pragma unroll
            for (int j = 0; j < 16; j++) zr[m][j] = 0.0f;
        }
    }

    __syncthreads();                 // all align-dot reads of sin_ complete
    if (is_z) {                      // z warps: cand = z * state, in place
#pragma unroll
        for (int m = 0; m < 2; m++) {
            float* row = &sin_[(rbase + lane + 32 * m) * SROW + 2 + e0];
#pragma unroll
            for (int j = 0; j < 16; j++) row[j] *= zr[m][j];
        }
    } else {                         // r warps: store r
#pragma unroll
        for (int m = 0; m < 2; m++) {
            int n = base + rbase + lane + 32 * m;
            if (n < NN) {
                float* rp = &g_r[((size_t)b * NN + n) * H + (e0 - 64)];
#pragma unroll
                for (int q = 0; q < 4; q++)
                    ((float4*)rp)[q] = make_float4(zr[m][4*q], zr[m][4*q+1],
                                                   zr[m][4*q+2], zr[m][4*q+3]);
            }
        }
    }
    __syncthreads();

    // ---- update dot on [x, z*state] ----
#pragma unroll
    for (int m = 0; m < 2; m++)
#pragma unroll
        for (int j = 0; j < 8; j++) acc[m][j] = 0ULL;
    dot64(sin_, sWu, rbase, lane, e0, acc);

    if (is_z) {                      // relu + column aggregate
        float colsum[16];
#pragma unroll
        for (int j = 0; j < 16; j++) colsum[j] = 0.0f;
#pragma unroll
        for (int m = 0; m < 2; m++) {
            int n = base + rbase + lane + 32 * m;
            if (n < NN) {
#pragma unroll
                for (int j = 0; j < 8; j++) {
                    float v0, v1; unpack2(acc[m][j], v0, v1);
                    colsum[2*j]   += fmaxf(v0 + sbu[e0 + 2*j],     0.0f);
                    colsum[2*j+1] += fmaxf(v1 + sbu[e0 + 2*j + 1], 0.0f);
                }
            }
        }
        colreduce_atomic(colsum, lane, &g_agg_upd[pg][b * H + e0]);
    } else {                         // res_upd store
#pragma unroll
        for (int m = 0; m < 2; m++) {
            int n = base + rbase + lane + 32 * m;
            if (n < NN) {
                float ru[16];
#pragma unroll
                for (int j = 0; j < 8; j++) {
                    float v0, v1; unpack2(acc[m][j], v0, v1);
                    ru[2*j]   = v0 + sbu[e0 + 2*j];
                    ru[2*j+1] = v1 + sbu[e0 + 2*j + 1];
                }
                float* rp = &g_resu[((size_t)b * NN + n) * H + (e0 - 64)];
#pragma unroll
                for (int q = 0; q < 4; q++)
                    ((float4*)rp)[q] = make_float4(ru[4*q], ru[4*q+1],
                                                   ru[4*q+2], ru[4*q+3]);
            }
        }
    }
}

// ===== K3: phase1 = h (coalesced, streams into out + sin_); phase2 = gate dot ==
__global__ void __launch_bounds__(NT, 2) k_final2(
    const float* __restrict__ state, int sstr,
    const float* __restrict__ x,
    const float* __restrict__ Wg, const float* __restrict__ bg,
    const float* __restrict__ affw, const float* __restrict__ affb,
    const float* __restrict__ nodew, const float* __restrict__ addw,
    float* __restrict__ out, int t, int pu, int pgn, int do_gate)
{
    float* sW   = sdyn;              // 66*128
    float* sb   = sW + KK * E2;      // 128
    float* sin_ = sb + E2;           // 128*67

    int tid = threadIdx.x;
    int b = blockIdx.y;
    int base = blockIdx.x * RPASS;

    if (do_gate) {
        for (int i = tid; i < KK * E2 / 4; i += NT)
            ((float4*)sW)[i] = ((const float4*)Wg)[i];
        if (tid < E2) sb[tid] = bg[tid];
    }

    const float* stb = state + (size_t)b * sstr;

    // -------- phase 1: h, fully coalesced float4 streams --------
#pragma unroll
    for (int p = 0; p < 4; p++) {
        int slot = p * NT + tid;             // 2048 slots = 128 rows x 16 float4
        int row = slot >> 4, q = (slot & 15) * 4;
        int n = base + row;
        float4 h4 = make_float4(0.f, 0.f, 0.f, 0.f);
        if (n < NN) {
            size_t ro = ((size_t)b * NN + n) * H + q;
            float4 r4 = *(const float4*)&g_r[ro];
            float4 u4 = *(const float4*)&g_resu[ro];
            float4 s4 = *(const float4*)(stb + (size_t)n * H + q);
            float  su = addw[n] * nodew[n];
            float4 a4 = *(const float4*)(affw + (size_t)n * H + q);
            float4 c4 = *(const float4*)(affb + (size_t)n * H + q);
            float4 g4 = *(const float4*)&g_agg_upd[pu][b * H + q];
            h4.x = r4.x*s4.x + (1.0f-r4.x)*tanhf(u4.x + a4.x*su*g4.x + c4.x);
            h4.y = r4.y*s4.y + (1.0f-r4.y)*tanhf(u4.y + a4.y*su*g4.y + c4.y);
            h4.z = r4.z*s4.z + (1.0f-r4.z)*tanhf(u4.z + a4.z*su*g4.z + c4.z);
            h4.w = r4.w*s4.w + (1.0f-r4.w)*tanhf(u4.w + a4.w*su*g4.w + c4.w);
            *(float4*)(out + ((size_t)(b * T + t) * NN + n) * H + q) = h4;
            if (t == T - 1)
                *(float4*)(out + OUT_LAST_OFF + ((size_t)b * NN + n) * H + q) = h4;
        }
        if (do_gate) {
            float* d = sin_ + row * SROW + 2 + q;
            d[0] = h4.x; d[1] = h4.y; d[2] = h4.z; d[3] = h4.w;
        }
    }
    if (!do_gate) return;
    if (tid < 256) {
        int row = tid >> 1, kx = tid & 1;
        int n = base + row;
        sin_[row * SROW + kx] = (n < NN)
            ? x[((size_t)(b * T + t + 1) * NN + n) * 2 + kx] : 0.0f;
    }
    __syncthreads();

    // -------- phase 2: gate dot for t+1 + relu aggregate --------
    int w = tid >> 5, lane = tid & 31;
    int rbase = (w >> 3) * 64, e0 = (w & 7) * 16;

    ull acc[2][8];
#pragma unroll
    for (int m = 0; m < 2; m++)
#pragma unroll
        for (int j = 0; j < 8; j++) acc[m][j] = 0ULL;
    dot64(sin_, sW, rbase, lane, e0, acc);

    float colsum[16];
#pragma unroll
    for (int j = 0; j < 16; j++) colsum[j] = 0.0f;
#pragma unroll
    for (int m = 0; m < 2; m++) {
        int n = base + rbase + lane + 32 * m;
        if (n < NN) {
#pragma unroll
            for (int j = 0; j < 8; j++) {
                float v0, v1; unpack2(acc[m][j], v0, v1);
                colsum[2*j]   += fmaxf(v0 + sb[e0 + 2*j],     0.0f);
                colsum[2*j+1] += fmaxf(v1 + sb[e0 + 2*j + 1], 0.0f);
            }
        }
    }
    colreduce_atomic(colsum, lane, &g_agg_gate[pgn][b * E2 + e0]);
}

// =============================== launch ========================================
extern "C" void kernel_launch(void* const* d_in, const int* in_sizes, int n_in,
                              void* d_out, int out_size)
{
    const float* x            = (const float*)d_in[0];
    const float* init_state   = (const float*)d_in[1];
    // d_in[2], d_in[3]: node_emb0/node_emb1 — unused by the reference
    const float* gate_align_w = (const float*)d_in[4];
    const float* gate_align_b = (const float*)d_in[5];
    const float* gate_w       = (const float*)d_in[6];
    const float* gate_b       = (const float*)d_in[7];
    const float* gate_node_w  = (const float*)d_in[8];
    const float* gate_add_w   = (const float*)d_in[9];
    const float* gate_aff_w   = (const float*)d_in[10];
    const float* gate_aff_b   = (const float*)d_in[11];
    const float* upd_align_w  = (const float*)d_in[12];
    const float* upd_align_b  = (const float*)d_in[13];
    const float* upd_w        = (const float*)d_in[14];
    const float* upd_b        = (const float*)d_in[15];
    const float* upd_node_w   = (const float*)d_in[16];
    const float* upd_add_w    = (const float*)d_in[17];
    const float* upd_aff_w    = (const float*)d_in[18];
    const float* upd_aff_b    = (const float*)d_in[19];
    float* out = (float*)d_out;

    int dyn_small = (KK * E2 + E2 + RPASS * SROW) * (int)sizeof(float);         // 68,608
    int dyn_mid   = (KK * E2 * 2 + E2 * 3 + RPASS * SROW) * (int)sizeof(float); // 103,424
    cudaFuncSetAttribute(k_gate_agg, cudaFuncAttributeMaxDynamicSharedMemorySize, dyn_small);
    cudaFuncSetAttribute(k_mid,      cudaFuncAttributeMaxDynamicSharedMemorySize, dyn_mid);
    cudaFuncSetAttribute(k_final2,   cudaFuncAttributeMaxDynamicSharedMemorySize, dyn_small);

    dim3 grid(CHUNKS, B);

    k_zero0<<<8, 256>>>();
    k_gate_agg<<<grid, NT, dyn_small>>>(x, init_state, NN * H, gate_w, gate_b, 0, 0);

    for (int t = 0; t < T; t++) {
        const float* state = (t == 0) ? init_state
                                      : (out + (size_t)(t - 1) * NN * H);
        int sstr = (t == 0) ? NN * H : T * NN * H;

        k_mid<<<grid, NT, dyn_mid>>>(x, state, sstr,
                                     gate_align_w, gate_align_b,
                                     upd_w, upd_b, upd_align_w, upd_align_b,
                                     gate_aff_w, gate_aff_b,
                                     gate_node_w, gate_add_w,
                                     t, t & 1, (t + 1) & 1);

        k_final2<<<grid, NT, dyn_small>>>(state, sstr, x, gate_w, gate_b,
                                          upd_aff_w, upd_aff_b,
                                          upd_node_w, upd_add_w,
                                          out, t, t & 1, (t + 1) & 1,
                                          (t < T - 1) ? 1 : 0);
    }
}